// round 16
// baseline (speedup 1.0000x reference)
#include <cuda_runtime.h>
#include <cstdint>

// ---------------- problem constants ----------------
#define BN   32
#define TN   4096
#define CINN 165
#define EDIM 64
#define NEMB 512
#define NTOK (BN*TN)          // 131072
#define TILE 32               // tokens per CTA
#define NBLK (NTOK/TILE)      // 4096
#define LDA  32               // token-row stride (floats) = 128B aligned
#define DEC_ELEMS (NTOK*CINN) // 21626880
#define THREADS 128

// shared layout (floats)
#define AROWS  288
#define SM_A   0
#define SM_W   (AROWS*LDA)          // 9216
#define WBUFF  4096
#define SM_AUX (SM_W + 2*WBUFF)     // 17408
#define SM_FLOATS (SM_AUX + 304)
#define SMEM_BYTES (SM_FLOATS*4)    // ~70.8 KB -> 3 CTAs/SM

typedef unsigned long long ULL;

__device__ float g_Wt[276480];
__device__ float g_bias[2432];
__device__ float g_enorm[NEMB];
__device__ float g_part[NBLK];
__device__ unsigned int g_count;

// layer metadata: {w_in_idx, b_in_idx, CIN, COUT, KPAD, CW, woff, boff}
__constant__ int c_layers[15][8] = {
    { 1,  2, 165, 128, 176, 128,      0,    0},
    { 3,  4, 128, 256, 128, 256,  22528,  128},
    { 5,  6, 256, 256, 256, 256,  55296,  384},
    { 7,  8, 256,  32, 256,  32, 120832,  640},
    { 9, 10,  32, 256,  32, 256, 129024,  672},
    {11, 12, 256,  32, 256,  32, 137216,  928},
    {13, 14,  32, 256,  32, 256, 145408,  960},
    {15, 16, 256,  64, 256,  64, 153600, 1216},
    {18, 19,  64, 256,  64, 256, 169984, 1280},
    {20, 21, 256,  32, 256,  32, 186368, 1536},
    {22, 23,  32, 256,  32, 256, 194560, 1568},
    {24, 25, 256,  32, 256,  32, 202752, 1824},
    {26, 27,  32, 256,  32, 256, 210944, 1856},
    {28, 29, 256, 128, 256, 128, 219136, 2112},
    {30, 31, 128, 165, 128, 192, 251904, 2240},
};

// ---------------- f32x2 helpers ----------------
__device__ __forceinline__ ULL pack2(float x, float y) {
    ULL r; asm("mov.b64 %0, {%1, %2};" : "=l"(r) : "f"(x), "f"(y)); return r;
}
__device__ __forceinline__ void unpack2(ULL v, float& x, float& y) {
    asm("mov.b64 {%0, %1}, %2;" : "=f"(x), "=f"(y) : "l"(v));
}
__device__ __forceinline__ void fma2(ULL& d, ULL a, ULL b) {
    asm("fma.rn.f32x2 %0, %1, %2, %0;" : "+l"(d) : "l"(a), "l"(b));
}
__device__ __forceinline__ uint32_t smem_u32(const void* p) {
    uint32_t a;
    asm("{ .reg .u64 t; cvta.to.shared.u64 t, %1; cvt.u32.u64 %0, t; }" : "=r"(a) : "l"(p));
    return a;
}
__device__ __forceinline__ void cp_async16(uint32_t dst, const void* src) {
    asm volatile("cp.async.cg.shared.global [%0], [%1], 16;\n" :: "r"(dst), "l"(src));
}

struct Params { const float* in[32]; float* out; int out_size; };

// ---------------- prep: weights transpose+pad, codebook norms ----------------
__global__ void prep_kernel(Params P) {
    const int L = blockIdx.x;
    if (L == 15) {
        const float* embed = P.in[17];
        for (int k = threadIdx.x; k < NEMB; k += blockDim.x) {
            float s = 0.f;
            for (int d = 0; d < EDIM; d++) { float e = embed[d * NEMB + k]; s += e * e; }
            g_enorm[k] = s;
        }
        return;
    }
    const int CIN  = c_layers[L][2], COUT = c_layers[L][3];
    const int KPAD = c_layers[L][4], CW   = c_layers[L][5];
    const int woff = c_layers[L][6], boff = c_layers[L][7];
    const float* W = P.in[c_layers[L][0]];
    const float* b = P.in[c_layers[L][1]];
    for (int e = threadIdx.x; e < KPAD * CW; e += blockDim.x) {
        int k = e / CW, c = e - (e / CW) * CW;
        float v = (k < CIN && c < COUT) ? W[c * CIN + k] : 0.f;
        g_Wt[woff + e] = v;
    }
    for (int c = threadIdx.x; c < CW; c += blockDim.x)
        g_bias[boff + c] = (c < COUT) ? b[c] : 0.f;
}

// ---------------- channel ownership (bank-conflict-free quads) ----------------
template<int MT>
__device__ __forceinline__ int chan(int ty, int m) {
    if constexpr (MT == 8) return (m < 4) ? ty * 4 + m : 128 + ty * 4 + (m - 4);
    else if constexpr (MT == 6) return (m < 4) ? ty * 4 + m : 128 + ty * 2 + (m - 4);
    else if constexpr (MT == 4) return ty * 4 + m;
    else return ty;
}

template<int MT>
__device__ __forceinline__ void load_wf(const float* Wrow, int ty, float* wf) {
    if constexpr (MT == 8) {
        float4 a = *reinterpret_cast<const float4*>(Wrow + ty * 4);
        float4 b = *reinterpret_cast<const float4*>(Wrow + 128 + ty * 4);
        wf[0] = a.x; wf[1] = a.y; wf[2] = a.z; wf[3] = a.w;
        wf[4] = b.x; wf[5] = b.y; wf[6] = b.z; wf[7] = b.w;
    } else if constexpr (MT == 6) {
        float4 a = *reinterpret_cast<const float4*>(Wrow + ty * 4);
        float2 b = *reinterpret_cast<const float2*>(Wrow + 128 + ty * 2);
        wf[0] = a.x; wf[1] = a.y; wf[2] = a.z; wf[3] = a.w;
        wf[4] = b.x; wf[5] = b.y;
    } else if constexpr (MT == 4) {
        float4 a = *reinterpret_cast<const float4*>(Wrow + ty * 4);
        wf[0] = a.x; wf[1] = a.y; wf[2] = a.z; wf[3] = a.w;
    }
}

// act token-pairs for 8 tokens at inr (32B aligned): PRE=false path is native
// ulonglong2 loads (ZERO pack MOVs); PRE=true must relu scalar then pack.
template<bool PRE>
__device__ __forceinline__ void load_act8(const float* inr, ULL* t) {
    if constexpr (!PRE) {
        ulonglong2 p0 = *reinterpret_cast<const ulonglong2*>(inr);
        ulonglong2 p1 = *reinterpret_cast<const ulonglong2*>(inr + 4);
        t[0] = p0.x; t[1] = p0.y; t[2] = p1.x; t[3] = p1.y;
    } else {
        float4 va = *reinterpret_cast<const float4*>(inr);
        float4 vb = *reinterpret_cast<const float4*>(inr + 4);
        va.x = fmaxf(va.x, 0.f); va.y = fmaxf(va.y, 0.f);
        va.z = fmaxf(va.z, 0.f); va.w = fmaxf(va.w, 0.f);
        vb.x = fmaxf(vb.x, 0.f); vb.y = fmaxf(vb.y, 0.f);
        vb.z = fmaxf(vb.z, 0.f); vb.w = fmaxf(vb.w, 0.f);
        t[0] = pack2(va.x, va.y); t[1] = pack2(va.z, va.w);
        t[2] = pack2(vb.x, vb.y); t[3] = pack2(vb.z, vb.w);
    }
}

// ---------------- fused 1x1-conv layer (wide channels: CW >= 128) ----------------
template<int CW, int KPAD, int KBT, bool PRE, bool POST, bool RES, bool STAGE>
__device__ __noinline__ void conv_layer(const float* __restrict__ Wt,
                                        const float* __restrict__ bias,
                                        const float* __restrict__ IN,
                                        float* __restrict__ OUT,
                                        float* __restrict__ Ws, int tid)
{
    constexpr int MT = CW / 32;
    constexpr int NK = KPAD / KBT;
    constexpr int CHUNKF = KBT * CW;
    static_assert(CHUNKF <= WBUFF, "chunk too big");

    const int tx = tid & 3;
    const int ty = tid >> 2;
    const int j0 = tx * 8;

    float bv[MT];
#pragma unroll
    for (int m = 0; m < MT; m++) bv[m] = __ldg(bias + chan<MT>(ty, m));

    ULL acc[4][MT];
#pragma unroll
    for (int t = 0; t < 4; t++)
#pragma unroll
        for (int m = 0; m < MT; m++) acc[t][m] = 0ull;

    __syncthreads();

    {
        const float4* src = reinterpret_cast<const float4*>(Wt);
        float4* dst = reinterpret_cast<float4*>(Ws);
#pragma unroll
        for (int i = tid; i < CHUNKF / 4; i += THREADS)
            cp_async16(smem_u32(dst + i), src + i);
        asm volatile("cp.async.commit_group;\n" ::: "memory");
    }

    for (int kb = 0; kb < NK; kb++) {
        asm volatile("cp.async.wait_group 0;\n" ::: "memory");
        __syncthreads();
        if (kb + 1 < NK) {
            const float4* src = reinterpret_cast<const float4*>(Wt + (kb + 1) * CHUNKF);
            float4* dst = reinterpret_cast<float4*>(Ws + ((kb + 1) & 1) * WBUFF);
#pragma unroll
            for (int i = tid; i < CHUNKF / 4; i += THREADS)
                cp_async16(smem_u32(dst + i), src + i);
            asm volatile("cp.async.commit_group;\n" ::: "memory");
        }

        const float* Wk  = Ws + (kb & 1) * WBUFF;
        const float* inb = IN + kb * KBT * LDA + j0;

#pragma unroll 8
        for (int kk = 0; kk < KBT; kk++) {
            ULL t[4];
            load_act8<PRE>(inb + kk * LDA, t);
            float wf[MT];
            load_wf<MT>(Wk + kk * CW, ty, wf);
#pragma unroll
            for (int m = 0; m < MT; m++) {
                ULL wd = pack2(wf[m], wf[m]);
                fma2(acc[0][m], wd, t[0]);
                fma2(acc[1][m], wd, t[1]);
                fma2(acc[2][m], wd, t[2]);
                fma2(acc[3][m], wd, t[3]);
            }
        }
    }

    if (STAGE) __syncthreads();

#pragma unroll
    for (int m = 0; m < MT; m++) {
        float r[8];
        unpack2(acc[0][m], r[0], r[1]);
        unpack2(acc[1][m], r[2], r[3]);
        unpack2(acc[2][m], r[4], r[5]);
        unpack2(acc[3][m], r[6], r[7]);
        float* op = OUT + chan<MT>(ty, m) * LDA + j0;
        float4 o0, o1;
        o0.x = r[0] + bv[m]; o0.y = r[1] + bv[m];
        o0.z = r[2] + bv[m]; o0.w = r[3] + bv[m];
        o1.x = r[4] + bv[m]; o1.y = r[5] + bv[m];
        o1.z = r[6] + bv[m]; o1.w = r[7] + bv[m];
        if (RES) {
            float4 e0 = *reinterpret_cast<float4*>(op);
            float4 e1 = *reinterpret_cast<float4*>(op + 4);
            o0.x += e0.x; o0.y += e0.y; o0.z += e0.z; o0.w += e0.w;
            o1.x += e1.x; o1.y += e1.y; o1.z += e1.z; o1.w += e1.w;
        }
        if (POST) {
            o0.x = fmaxf(o0.x, 0.f); o0.y = fmaxf(o0.y, 0.f);
            o0.z = fmaxf(o0.z, 0.f); o0.w = fmaxf(o0.w, 0.f);
            o1.x = fmaxf(o1.x, 0.f); o1.y = fmaxf(o1.y, 0.f);
            o1.z = fmaxf(o1.z, 0.f); o1.w = fmaxf(o1.w, 0.f);
        }
        *reinterpret_cast<float4*>(op)     = o0;
        *reinterpret_cast<float4*>(op + 4) = o1;
    }
}

// ---------------- fused 1x1-conv layer (narrow: CW = 32 or 64, k-split) ----------------
template<int CW, int KPAD, bool PRE, bool POST>
__device__ __noinline__ void conv_small(const float* __restrict__ Wt,
                                        const float* __restrict__ bias,
                                        const float* __restrict__ IN,
                                        float* __restrict__ OUT,
                                        float* __restrict__ Ws, int tid)
{
    constexpr int KS   = (CW == 32) ? 4 : 2;
    constexpr int KLEN = KPAD / KS;
    constexpr int PROW = CW * 33;
    static_assert(KS * PROW <= 2 * WBUFF, "partials too big");

    const int w = tid >> 5, l = tid & 31;
    const int ks  = (CW == 32) ? w : (w >> 1);
    const int chg = (CW == 32) ? (l & 7) : (((w & 1) << 3) | (l & 7));
    const int tg  = l >> 3;
    const int j0  = tg * 8;
    const int ch0 = chg * 4;
    const int k0  = ks * KLEN;

    ULL acc[4][4];
#pragma unroll
    for (int t = 0; t < 4; t++)
#pragma unroll
        for (int m = 0; m < 4; m++) acc[t][m] = 0ull;

    __syncthreads();

#pragma unroll 8
    for (int kk = 0; kk < KLEN; kk++) {
        int k = k0 + kk;
        ULL t[4];
        load_act8<PRE>(IN + k * LDA + j0, t);
        float4 wq = __ldg(reinterpret_cast<const float4*>(Wt + k * CW + ch0));
        float wf[4] = {wq.x, wq.y, wq.z, wq.w};
#pragma unroll
        for (int m = 0; m < 4; m++) {
            ULL wd = pack2(wf[m], wf[m]);
            fma2(acc[0][m], wd, t[0]);
            fma2(acc[1][m], wd, t[1]);
            fma2(acc[2][m], wd, t[2]);
            fma2(acc[3][m], wd, t[3]);
        }
    }

    float* Pp = Ws + ks * PROW;
#pragma unroll
    for (int m = 0; m < 4; m++) {
        float r[8];
        unpack2(acc[0][m], r[0], r[1]);
        unpack2(acc[1][m], r[2], r[3]);
        unpack2(acc[2][m], r[4], r[5]);
        unpack2(acc[3][m], r[6], r[7]);
        float* pp = Pp + (ch0 + m) * 33 + j0;
#pragma unroll
        for (int n = 0; n < 8; n++) pp[n] = r[n];
    }
    __syncthreads();

    constexpr int NO = CW * 32 / THREADS;
#pragma unroll
    for (int i = 0; i < NO; i++) {
        int o = tid * NO + i;
        int ch = o >> 5, j = o & 31;
        float s = 0.f;
#pragma unroll
        for (int q = 0; q < KS; q++) s += Ws[q * PROW + ch * 33 + j];
        s += __ldg(bias + ch);
        if (POST) s = fmaxf(s, 0.f);
        OUT[ch * LDA + j] = s;
    }
}

#define LCONV(L, CW, KPAD, KBT, PRE, POST, RES, STAGE, INB, OUTB) \
    conv_layer<CW, KPAD, KBT, PRE, POST, RES, STAGE>(g_Wt + c_layers[L][6], g_bias + c_layers[L][7], INB, OUTB, Ws, tid)
#define LCONVS(L, CW, KPAD, PRE, POST, INB, OUTB) \
    conv_small<CW, KPAD, PRE, POST>(g_Wt + c_layers[L][6], g_bias + c_layers[L][7], INB, OUTB, Ws, tid)

// ---------------- main fused kernel ----------------
__global__ void __launch_bounds__(THREADS, 3) vqvae_kernel(Params P)
{
    extern __shared__ float sm[];
    float* A    = sm + SM_A;
    float* T32  = A + 256 * LDA;
    float* Ws   = sm + SM_W;
    float* cand_d = sm + SM_AUX;
    float* cand_i = cand_d + 128;
    float* ibest  = cand_i + 128;
    float* wsum   = ibest + 32;

    const int tid = threadIdx.x;
    const int n0  = blockIdx.x * TILE;

    // ---- input: coalesced gmem read -> padded Ws tile -> conflict-free A write ----
    {
        const float* x = P.in[0];
        for (int idx = tid; idx < 176 * TILE; idx += THREADS) {
            int j = idx / 176;
            int c = idx - j * 176;
            Ws[j * 177 + c] = (c < CINN) ? x[(n0 + j) * CINN + c] : 0.f;
        }
        __syncthreads();
        for (int idx = tid; idx < 176 * TILE; idx += THREADS) {
            int c = idx >> 5;
            int j = idx & 31;
            A[c * LDA + j] = Ws[j * 177 + c];
        }
    }

    // ---- encoder ----
    LCONV (0, 128, 176, 16, false, true,  false, true,  A,   A  );
    LCONV (1, 256, 128, 16, false, true,  false, true,  A,   A  );
    LCONV (2, 256, 256, 16, false, false, false, true,  A,   A  );
    LCONVS(3,  32, 256, true, true,  A,   T32);
    LCONV (4, 256,  32, 16, false, false, true,  false, T32, A  );
    LCONVS(5,  32, 256, true, true,  A,   T32);
    LCONV (6, 256,  32, 16, false, false, true,  false, T32, A  );
    LCONVS(7,  64, 256, true, false, A,   A  );   // z -> rows 0..63

    // ---- vector quantize ----
    {
        const float* embed = P.in[17];
        const int l = tid & 31;
        const int w = tid >> 5;
        const int cgrp = l >> 2;
        const int jgrp = l & 3;
        const int j0v = jgrp * 8;

        __syncthreads();

        float best[8]; int bidx[8];
#pragma unroll
        for (int t = 0; t < 8; t++) { best[t] = 3.4e38f; bidx[t] = 0; }

#pragma unroll
        for (int cbi = 0; cbi < 2; cbi++) {
            const int cb = w * 2 + cbi;
            const int cbase = cb * 64 + cgrp * 8;

            ULL acc[4][8];
#pragma unroll
            for (int c2 = 0; c2 < 4; c2++)
#pragma unroll
                for (int t = 0; t < 8; t++) acc[c2][t] = 0ull;

#pragma unroll 8
            for (int d = 0; d < EDIM; d++) {
                const float* zr = A + d * LDA + j0v;
                float4 za = *reinterpret_cast<const float4*>(zr);
                float4 zb = *reinterpret_cast<const float4*>(zr + 4);
                ULL zd[8];
                zd[0] = pack2(za.x, za.x); zd[1] = pack2(za.y, za.y);
                zd[2] = pack2(za.z, za.z); zd[3] = pack2(za.w, za.w);
                zd[4] = pack2(zb.x, zb.x); zd[5] = pack2(zb.y, zb.y);
                zd[6] = pack2(zb.z, zb.z); zd[7] = pack2(zb.w, zb.w);
                const ulonglong2* ep =
                    reinterpret_cast<const ulonglong2*>(embed + d * NEMB + cbase);
                ulonglong2 e01 = __ldg(ep), e23 = __ldg(ep + 1);
                ULL ec[4] = {e01.x, e01.y, e23.x, e23.y};
#pragma unroll
                for (int c2 = 0; c2 < 4; c2++)
#pragma unroll
                    for (int t = 0; t < 8; t++)
                        fma2(acc[c2][t], ec[c2], zd[t]);
            }

            float4 en0 = __ldg(reinterpret_cast<const float4*>(g_enorm + cbase));
            float4 en1 = __ldg(reinterpret_cast<const float4*>(g_enorm + cbase + 4));
            float en[8] = {en0.x, en0.y, en0.z, en0.w, en1.x, en1.y, en1.z, en1.w};
#pragma unroll
            for (int c2 = 0; c2 < 4; c2++) {
                int c = cbase + c2 * 2;
#pragma unroll
                for (int t = 0; t < 8; t++) {
                    float d0, d1; unpack2(acc[c2][t], d0, d1);
                    float s0 = en[c2 * 2]     - 2.f * d0;
                    float s1 = en[c2 * 2 + 1] - 2.f * d1;
                    if (s0 < best[t]) { best[t] = s0; bidx[t] = c; }
                    if (s1 < best[t]) { best[t] = s1; bidx[t] = c + 1; }
                }
            }
        }

#pragma unroll
        for (int off = 4; off < 32; off <<= 1) {
#pragma unroll
            for (int t = 0; t < 8; t++) {
                float ob = __shfl_xor_sync(0xffffffffu, best[t], off);
                int   oi = __shfl_xor_sync(0xffffffffu, bidx[t], off);
                if (ob < best[t] || (ob == best[t] && oi < bidx[t])) {
                    best[t] = ob; bidx[t] = oi;
                }
            }
        }
        if (cgrp == 0) {
#pragma unroll
            for (int t = 0; t < 8; t++) {
                cand_d[w * 32 + j0v + t] = best[t];
                reinterpret_cast<int*>(cand_i)[w * 32 + j0v + t] = bidx[t];
            }
        }
        __syncthreads();
        if (tid < 32) {
            float bb = cand_d[tid];
            int   bi = reinterpret_cast<int*>(cand_i)[tid];
#pragma unroll
            for (int ww = 1; ww < 4; ww++) {
                float ob = cand_d[ww * 32 + tid];
                int   oi = reinterpret_cast<int*>(cand_i)[ww * 32 + tid];
                if (ob < bb || (ob == bb && oi < bi)) { bb = ob; bi = oi; }
            }
            reinterpret_cast<int*>(ibest)[tid] = bi;
        }
        __syncthreads();

        const int j = tid >> 2;
        const int q = tid & 3;
        const int bsel = reinterpret_cast<int*>(ibest)[j];
        float dsum = 0.f;
#pragma unroll
        for (int dd = 0; dd < 16; dd++) {
            int d = q * 16 + dd;
            float e = __ldg(embed + d * NEMB + bsel);
            float z = A[d * LDA + j];
            A[d * LDA + j] = e;
            float df = e - z;
            dsum += df * df;
        }
#pragma unroll
        for (int off = 16; off > 0; off >>= 1)
            dsum += __shfl_xor_sync(0xffffffffu, dsum, off);
        if ((tid & 31) == 0) wsum[tid >> 5] = dsum;
        __syncthreads();
        if (tid == 0)
            g_part[blockIdx.x] = wsum[0] + wsum[1] + wsum[2] + wsum[3];
    }

    // ---- decoder ----
    LCONV (8, 256,  64, 16, false, false, false, true,  A,   A  );
    LCONVS(9,  32, 256, true, true,  A,   T32);
    LCONV (10, 256, 32, 16, false, false, true,  false, T32, A  );
    LCONVS(11, 32, 256, true, true,  A,   T32);
    LCONV (12, 256, 32, 16, false, false, true,  false, T32, A  );
    LCONV (13, 128, 256, 32, true, true,  false, true,  A,   A  );
    LCONV (14, 192, 128, 16, false, false, false, true,  A,   A  );
    __syncthreads();

    // ---- output: conflict-free A read -> padded Ws tile -> coalesced gmem write ----
    {
        for (int idx = tid; idx < CINN * 32; idx += THREADS) {
            int c = idx >> 5;
            int j = idx & 31;
            Ws[j * 167 + c] = A[c * LDA + j];
        }
        __syncthreads();
        for (int idx = tid; idx < CINN * TILE; idx += THREADS) {
            int j = idx / CINN;
            int c = idx - j * CINN;
            P.out[(n0 + j) * CINN + c] = Ws[j * 167 + c];
        }
    }

    // ---- last-block finalize of diff ----
    __threadfence();
    __shared__ unsigned int is_last;
    if (tid == 0) is_last = (atomicAdd(&g_count, 1u) == NBLK - 1) ? 1u : 0u;
    __syncthreads();
    if (is_last) {
        float s = 0.f;
        for (int i = tid; i < NBLK; i += THREADS) s += g_part[i];
#pragma unroll
        for (int off = 16; off > 0; off >>= 1)
            s += __shfl_xor_sync(0xffffffffu, s, off);
        if ((tid & 31) == 0) wsum[tid >> 5] = s;
        __syncthreads();
        if (tid == 0) {
            float t = wsum[0] + wsum[1] + wsum[2] + wsum[3];
            if (P.out_size > DEC_ELEMS)
                P.out[DEC_ELEMS] = t * (1.0f / 8388608.0f);
            g_count = 0u;
        }
    }
}

// ---------------- launch ----------------
extern "C" void kernel_launch(void* const* d_in, const int* in_sizes, int n_in,
                              void* d_out, int out_size)
{
    (void)in_sizes; (void)n_in;
    Params P;
    for (int i = 0; i < 32; i++) P.in[i] = (const float*)d_in[i];
    P.out = (float*)d_out;
    P.out_size = out_size;

    static bool attr_set = false;
    if (!attr_set) {
        cudaFuncSetAttribute(vqvae_kernel, cudaFuncAttributeMaxDynamicSharedMemorySize, SMEM_BYTES);
        attr_set = true;
    }
    prep_kernel<<<16, 256>>>(P);
    vqvae_kernel<<<NBLK, THREADS, SMEM_BYTES>>>(P);
}